// round 1
// baseline (speedup 1.0000x reference)
#include <cuda_runtime.h>

#define HWN   4096
#define CDIM  256
#define KCODES 1024
#define BATCH 16

// Device-global scratch (no allocations allowed in kernel_launch)
__device__ float g_ct[CDIM * KCODES];   // codebook transposed [c][k], 1 MB
__device__ float g_c2[KCODES];          // ||codebook_k||^2
__device__ int   g_inds[BATCH * HWN];   // argmin indices
__device__ float g_loss;                // loss accumulator

// ---------------------------------------------------------------------------
// Prep 1: tiled transpose codebook[k][c] -> g_ct[c][k]; also zero g_loss.
// ---------------------------------------------------------------------------
__global__ void prep_transpose(const float* __restrict__ cb) {
    __shared__ float tile[32][33];
    int k0 = blockIdx.x * 32;
    int c0 = blockIdx.y * 32;
    int tx = threadIdx.x & 31;
    int r0 = threadIdx.x >> 5;  // 0..7
#pragma unroll
    for (int i = 0; i < 4; i++) {
        int k = r0 + i * 8;
        tile[k][tx] = cb[(size_t)(k0 + k) * CDIM + c0 + tx];
    }
    __syncthreads();
#pragma unroll
    for (int i = 0; i < 4; i++) {
        int c = r0 + i * 8;
        g_ct[(size_t)(c0 + c) * KCODES + k0 + tx] = tile[tx][c];
    }
    if (blockIdx.x == 0 && blockIdx.y == 0 && threadIdx.x == 0) g_loss = 0.0f;
}

// ---------------------------------------------------------------------------
// Prep 2: c2[k] = sum_c codebook[k][c]^2   (one warp per code row)
// ---------------------------------------------------------------------------
__global__ void prep_c2(const float* __restrict__ cb) {
    int k = blockIdx.x;
    int lane = threadIdx.x;
    float s = 0.0f;
#pragma unroll
    for (int c = lane; c < CDIM; c += 32) {
        float v = cb[(size_t)k * CDIM + c];
        s += v * v;
    }
#pragma unroll
    for (int o = 16; o; o >>= 1) s += __shfl_xor_sync(0xffffffffu, s, o);
    if (lane == 0) g_c2[k] = s;
}

// ---------------------------------------------------------------------------
// SGEMM + argmin.
// Block: 256 threads, computes 64 pixels x all 1024 codes.
// Tiles: TM=64 px, TN=64 codes, TK=32 channels. 4x4 register microtile.
// d2[k] = c2[k] - 2*dot(x_n, c_k)  (||x||^2 constant per row, irrelevant
// for argmin; loss computed later from actual (q-x)^2)
// ---------------------------------------------------------------------------
__global__ __launch_bounds__(256) void gemm_argmin(const float* __restrict__ x) {
    __shared__ float As[32][64];
    __shared__ float Bs[32][64];
    __shared__ float rv[64][17];
    __shared__ int   ri[64][17];

    const int b  = blockIdx.y;
    const int n0 = blockIdx.x * 64;
    const int tid = threadIdx.x;
    const int tx = tid & 15;        // code dim (4 codes each)
    const int ty = tid >> 4;        // pixel dim (4 px each)
    const int lcol = tid & 63;      // loader column
    const int lrow = tid >> 6;      // loader row base (0..3)

    const float* xb = x + (size_t)b * CDIM * HWN + n0;

    float best[4];
    int   besti[4];
#pragma unroll
    for (int i = 0; i < 4; i++) { best[i] = 3.4e38f; besti[i] = 0; }

    for (int kt = 0; kt < KCODES / 64; kt++) {
        float acc[4][4];
#pragma unroll
        for (int i = 0; i < 4; i++)
#pragma unroll
            for (int j = 0; j < 4; j++) acc[i][j] = 0.0f;

#pragma unroll 1
        for (int cc = 0; cc < CDIM; cc += 32) {
#pragma unroll
            for (int i = 0; i < 8; i++) {
                int r = lrow + i * 4;
                As[r][lcol] = xb[(size_t)(cc + r) * HWN + lcol];
                Bs[r][lcol] = g_ct[(size_t)(cc + r) * KCODES + kt * 64 + lcol];
            }
            __syncthreads();
#pragma unroll
            for (int c = 0; c < 32; c++) {
                float4 a  = *(const float4*)&As[c][ty * 4];
                float4 bq = *(const float4*)&Bs[c][tx * 4];
                acc[0][0] = fmaf(a.x, bq.x, acc[0][0]);
                acc[0][1] = fmaf(a.x, bq.y, acc[0][1]);
                acc[0][2] = fmaf(a.x, bq.z, acc[0][2]);
                acc[0][3] = fmaf(a.x, bq.w, acc[0][3]);
                acc[1][0] = fmaf(a.y, bq.x, acc[1][0]);
                acc[1][1] = fmaf(a.y, bq.y, acc[1][1]);
                acc[1][2] = fmaf(a.y, bq.z, acc[1][2]);
                acc[1][3] = fmaf(a.y, bq.w, acc[1][3]);
                acc[2][0] = fmaf(a.z, bq.x, acc[2][0]);
                acc[2][1] = fmaf(a.z, bq.y, acc[2][1]);
                acc[2][2] = fmaf(a.z, bq.z, acc[2][2]);
                acc[2][3] = fmaf(a.z, bq.w, acc[2][3]);
                acc[3][0] = fmaf(a.w, bq.x, acc[3][0]);
                acc[3][1] = fmaf(a.w, bq.y, acc[3][1]);
                acc[3][2] = fmaf(a.w, bq.z, acc[3][2]);
                acc[3][3] = fmaf(a.w, bq.w, acc[3][3]);
            }
            __syncthreads();
        }

        // epilogue: running argmin (ascending k order -> first-min semantics)
#pragma unroll
        for (int j = 0; j < 4; j++) {
            int k = kt * 64 + tx * 4 + j;
            float c2v = g_c2[k];
#pragma unroll
            for (int i = 0; i < 4; i++) {
                float d = fmaf(-2.0f, acc[i][j], c2v);
                if (d < best[i]) { best[i] = d; besti[i] = k; }
            }
        }
    }

    // cross-thread (tx) argmin reduce per pixel
#pragma unroll
    for (int i = 0; i < 4; i++) {
        rv[ty * 4 + i][tx] = best[i];
        ri[ty * 4 + i][tx] = besti[i];
    }
    __syncthreads();
    if (tid < 64) {
        float bv = 3.4e38f;
        int bi = 0x7fffffff;
#pragma unroll
        for (int t = 0; t < 16; t++) {
            float v = rv[tid][t];
            int id = ri[tid][t];
            if (v < bv || (v == bv && id < bi)) { bv = v; bi = id; }
        }
        g_inds[b * HWN + n0 + tid] = bi;
    }
}

// ---------------------------------------------------------------------------
// Gather: out[b][c][n] = codebook[ind[b][n]][c]; accumulate (q - x)^2.
// Block: 64 pixels x all 256 channels. Warps coalesced along n.
// ---------------------------------------------------------------------------
__global__ __launch_bounds__(256) void gather_loss(const float* __restrict__ x,
                                                   const float* __restrict__ cb,
                                                   float* __restrict__ out) {
    int t = blockIdx.x;
    int b  = t >> 6;
    int n0 = (t & 63) * 64;
    int nl = threadIdx.x & 63;
    int c0 = threadIdx.x >> 6;   // 0..3

    int idx = g_inds[b * HWN + n0 + nl];
    const float* crow = cb + (size_t)idx * CDIM;
    const float* xb   = x   + (size_t)b * CDIM * HWN + n0 + nl;
    float*       ob   = out + (size_t)b * CDIM * HWN + n0 + nl;

    float lsum = 0.0f;
#pragma unroll 8
    for (int i = 0; i < 64; i++) {
        int c = c0 + i * 4;
        float q  = __ldg(crow + c);
        float xv = xb[(size_t)c * HWN];
        ob[(size_t)c * HWN] = q;
        float d = q - xv;
        lsum += d * d;
    }
#pragma unroll
    for (int o = 16; o; o >>= 1) lsum += __shfl_xor_sync(0xffffffffu, lsum, o);
    __shared__ float ws[8];
    if ((threadIdx.x & 31) == 0) ws[threadIdx.x >> 5] = lsum;
    __syncthreads();
    if (threadIdx.x == 0) {
        float s = 0.0f;
#pragma unroll
        for (int w = 0; w < 8; w++) s += ws[w];
        atomicAdd(&g_loss, s);
    }
}

// ---------------------------------------------------------------------------
// Finalize: loss = sum / (B*N*C) * commitment_weight(=1)
// ---------------------------------------------------------------------------
__global__ void finalize_loss(float* __restrict__ out, int loss_off) {
    out[loss_off] = g_loss * (1.0f / (float)(BATCH * HWN * CDIM));
}

extern "C" void kernel_launch(void* const* d_in, const int* in_sizes, int n_in,
                              void* d_out, int out_size) {
    const float* x  = (const float*)d_in[0];   // [16, 256, 64, 64]
    const float* cb = (const float*)d_in[1];   // [1024, 256]
    float* out = (float*)d_out;                // [16*256*64*64] quantized + [1] loss

    prep_transpose<<<dim3(KCODES / 32, CDIM / 32), 256>>>(cb);
    prep_c2<<<KCODES, 32>>>(cb);
    gemm_argmin<<<dim3(HWN / 64, BATCH), 256>>>(x);
    gather_loss<<<BATCH * HWN / 64, 256>>>(x, cb, out);
    finalize_loss<<<1, 1>>>(out, out_size - 1);
}